// round 1
// baseline (speedup 1.0000x reference)
#include <cuda_runtime.h>

// MemristorLinearLayer reduces algebraically to: out = x @ W^T + bias.
//   V@G_pos - V@G_neg = V@(G_pos - G_neg) = V@(k_G*wb); dividing by k_I = K_V*k_G
//   cancels every memristor constant. bias occupies the appended "ones" column.
//
// Shapes (fixed by the dataset): x[512][2048] f32, W[2048][2048] f32 (row-major,
// K contiguous -> NT GEMM), bias[2048] f32, out[512][2048] f32.

namespace {
constexpr int M = 512;
constexpr int N = 2048;
constexpr int K = 2048;
constexpr int BM = 64;
constexpr int BN = 128;
constexpr int BK = 16;
}  // namespace

__global__ __launch_bounds__(256, 1)
void memristor_gemm_kernel(const float* __restrict__ X,
                           const float* __restrict__ W,
                           const float* __restrict__ bias,
                           float* __restrict__ O)
{
    // +4 padding keeps float4 alignment (stride*4 % 16 == 0) and limits store
    // conflicts to 2-way.
    __shared__ float As[BK][BM + 4];   // As[k][m]
    __shared__ float Bs[BK][BN + 4];   // Bs[k][n]

    const int t  = threadIdx.x;
    const int tx = t & 15;   // 16 threads across N, 8 cols each
    const int ty = t >> 4;   // 16 threads across M, 4 rows each
    const int m0 = blockIdx.y * BM;
    const int n0 = blockIdx.x * BN;

    // A tile: 64 rows x 16 k = 256 float4 -> 1 per thread.
    const int a_row = t >> 2;          // 0..63
    const int a_kv  = (t & 3) << 2;    // 0,4,8,12
    const float* a_ptr = X + (size_t)(m0 + a_row) * K + a_kv;

    // B tile: 128 rows x 16 k = 512 float4 -> 2 per thread (rows r and r+64).
    const int b_row = t >> 2;          // 0..63
    const int b_kv  = (t & 3) << 2;
    const float* b_ptr0 = W + (size_t)(n0 + b_row) * K + b_kv;
    const float* b_ptr1 = W + (size_t)(n0 + b_row + 64) * K + b_kv;

    float acc[4][8];
    #pragma unroll
    for (int i = 0; i < 4; ++i)
        #pragma unroll
        for (int j = 0; j < 8; ++j) acc[i][j] = 0.0f;

    // Prefetch tile 0 into registers.
    float4 a_reg  = *reinterpret_cast<const float4*>(a_ptr);
    float4 b_reg0 = *reinterpret_cast<const float4*>(b_ptr0);
    float4 b_reg1 = *reinterpret_cast<const float4*>(b_ptr1);

    for (int k0 = 0; k0 < K; k0 += BK) {
        // Stage registers -> shared (transposed).
        As[a_kv + 0][a_row] = a_reg.x;
        As[a_kv + 1][a_row] = a_reg.y;
        As[a_kv + 2][a_row] = a_reg.z;
        As[a_kv + 3][a_row] = a_reg.w;
        Bs[b_kv + 0][b_row] = b_reg0.x;
        Bs[b_kv + 1][b_row] = b_reg0.y;
        Bs[b_kv + 2][b_row] = b_reg0.z;
        Bs[b_kv + 3][b_row] = b_reg0.w;
        Bs[b_kv + 0][b_row + 64] = b_reg1.x;
        Bs[b_kv + 1][b_row + 64] = b_reg1.y;
        Bs[b_kv + 2][b_row + 64] = b_reg1.z;
        Bs[b_kv + 3][b_row + 64] = b_reg1.w;
        __syncthreads();

        // Issue next tile's global loads early so their latency hides under
        // the FFMA block below.
        if (k0 + BK < K) {
            a_reg  = *reinterpret_cast<const float4*>(a_ptr  + k0 + BK);
            b_reg0 = *reinterpret_cast<const float4*>(b_ptr0 + k0 + BK);
            b_reg1 = *reinterpret_cast<const float4*>(b_ptr1 + k0 + BK);
        }

        #pragma unroll
        for (int kk = 0; kk < BK; ++kk) {
            const float4 a01 = *reinterpret_cast<const float4*>(&As[kk][ty * 4]);
            const float4 b01 = *reinterpret_cast<const float4*>(&Bs[kk][tx * 8]);
            const float4 b23 = *reinterpret_cast<const float4*>(&Bs[kk][tx * 8 + 4]);
            const float a[4] = {a01.x, a01.y, a01.z, a01.w};
            const float b[8] = {b01.x, b01.y, b01.z, b01.w,
                                b23.x, b23.y, b23.z, b23.w};
            #pragma unroll
            for (int i = 0; i < 4; ++i)
                #pragma unroll
                for (int j = 0; j < 8; ++j)
                    acc[i][j] = fmaf(a[i], b[j], acc[i][j]);
        }
        __syncthreads();
    }

    // Epilogue: add bias, vectorized stores.
    const int ncol = n0 + tx * 8;
    float bb[8];
    #pragma unroll
    for (int j = 0; j < 8; ++j) bb[j] = bias[ncol + j];

    #pragma unroll
    for (int i = 0; i < 4; ++i) {
        const int m = m0 + ty * 4 + i;
        float4 o0 = {acc[i][0] + bb[0], acc[i][1] + bb[1],
                     acc[i][2] + bb[2], acc[i][3] + bb[3]};
        float4 o1 = {acc[i][4] + bb[4], acc[i][5] + bb[5],
                     acc[i][6] + bb[6], acc[i][7] + bb[7]};
        *reinterpret_cast<float4*>(&O[(size_t)m * N + ncol])     = o0;
        *reinterpret_cast<float4*>(&O[(size_t)m * N + ncol + 4]) = o1;
    }
}

extern "C" void kernel_launch(void* const* d_in, const int* in_sizes, int n_in,
                              void* d_out, int out_size)
{
    (void)in_sizes; (void)n_in; (void)out_size;
    const float* x    = (const float*)d_in[0];
    const float* w    = (const float*)d_in[1];
    const float* bias = (const float*)d_in[2];
    float* out        = (float*)d_out;

    dim3 grid(N / BN, M / BM);   // 16 x 8 = 128 blocks
    memristor_gemm_kernel<<<grid, 256>>>(x, w, bias, out);
}

// round 6
// speedup vs baseline: 3.9529x; 3.9529x over previous
#include <cuda_runtime.h>
#include <cuda_fp16.h>
#include <cstdint>

// out = x @ W^T + bias  (memristor constants cancel algebraically; see R1).
//
// The harness compiles PTX at target compute_103 (no 'a'), so tcgen05/TMEM are
// unavailable. Use legacy tensor-core path: mma.sync.m16n8k16 (HMMA) + ldmatrix.
//
// 2-term fp16 split:  out ~= A_hi@(B_hi + B_lo),  B scaled by 256 (exact pow2)
// so residuals stay fp16-normal; 1/256 folded into the epilogue. Dropped error
// is a_lo*b ~ 2^-11.8 relative -> norm rel_err ~3e-4 << 1e-3.
//
// x[512][2048] f32, W[2048][2048] f32 (K contiguous -> NT GEMM), out[512][2048].

namespace {
constexpr int M = 512, N = 2048, K = 2048;
constexpr int BM = 64, BN = 128, BK = 32;
constexpr int NT = K / BK;                 // 64 k-tiles
constexpr int ROWB = 80;                   // 32 halves (64B) + 16B pad: conflict-free LDSM
constexpr int A_SZ   = BM * ROWB;          // 5120
constexpr int B_SZ   = BN * ROWB;          // 10240
constexpr int OFF_BH = A_SZ;               // 5120
constexpr int OFF_BL = A_SZ + B_SZ;        // 15360
constexpr int STAGE  = A_SZ + 2 * B_SZ;    // 25600
constexpr int SMEM_TOTAL = 2 * STAGE;      // 51200 (dynamic; > 48K static limit)
constexpr float BSCALE = 256.0f;
constexpr float OSCALE = 1.0f / 256.0f;
}  // namespace

__device__ __forceinline__ unsigned smem_u32(const void* p) {
    unsigned a;
    asm("{ .reg .u64 t; cvta.to.shared.u64 t, %1; cvt.u32.u64 %0, t; }"
        : "=r"(a) : "l"(p));
    return a;
}

__device__ __forceinline__ void ldsm4(unsigned r[4], unsigned addr) {
    asm volatile("ldmatrix.sync.aligned.m8n8.x4.shared.b16 {%0,%1,%2,%3}, [%4];"
                 : "=r"(r[0]), "=r"(r[1]), "=r"(r[2]), "=r"(r[3]) : "r"(addr));
}

__device__ __forceinline__ void mma16816(float d[4], const unsigned a[4],
                                         const unsigned b[2]) {
    asm volatile(
        "mma.sync.aligned.m16n8k16.row.col.f32.f16.f16.f32 "
        "{%0,%1,%2,%3}, {%4,%5,%6,%7}, {%8,%9}, {%0,%1,%2,%3};"
        : "+f"(d[0]), "+f"(d[1]), "+f"(d[2]), "+f"(d[3])
        : "r"(a[0]), "r"(a[1]), "r"(a[2]), "r"(a[3]), "r"(b[0]), "r"(b[1]));
}

// Pack float4 -> two f16x2 words (memory order x,y,z,w).
__device__ __forceinline__ uint2 pack_f16x4(float4 v) {
    unsigned h0, h1;
    asm("cvt.rn.f16x2.f32 %0, %1, %2;" : "=r"(h0) : "f"(v.y), "f"(v.x));
    asm("cvt.rn.f16x2.f32 %0, %1, %2;" : "=r"(h1) : "f"(v.w), "f"(v.z));
    return make_uint2(h0, h1);
}

__global__ __launch_bounds__(256, 1)
void memristor_hmma_kernel(const float* __restrict__ X, const float* __restrict__ W,
                           const float* __restrict__ bias, float* __restrict__ O)
{
    extern __shared__ char smem[];
    const unsigned sb = smem_u32(smem);
    const int t = threadIdx.x;
    const int lane = t & 31, wid = t >> 5;
    const int wm = wid & 1, wn = wid >> 1;        // warp grid 2(M) x 4(N)
    const int m0 = blockIdx.y * BM, n0 = blockIdx.x * BN;

    // ---- global-load mapping: 8 float4 per row of 32 f32 ----
    const int lr = t >> 3;                        // 0..31
    const int lc = t & 7;                         // float4 column
    const float* aP = X + (size_t)(m0 + lr) * K + lc * 4;
    const float* bP = W + (size_t)(n0 + lr) * K + lc * 4;

    float4 aR[2], bR[4];
    auto LOAD = [&](int it) {
        const int k0 = it * BK;
        aR[0] = *reinterpret_cast<const float4*>(aP + k0);
        aR[1] = *reinterpret_cast<const float4*>(aP + (size_t)32 * K + k0);
        #pragma unroll
        for (int j = 0; j < 4; ++j)
            bR[j] = *reinterpret_cast<const float4*>(bP + (size_t)(32 * j) * K + k0);
    };

    auto STORE = [&](int buf) {
        char* base = smem + buf * STAGE;
        #pragma unroll
        for (int j = 0; j < 2; ++j) {             // A: hi only
            uint2 h = pack_f16x4(aR[j]);
            *reinterpret_cast<uint2*>(base + (lr + 32 * j) * ROWB + lc * 8) = h;
        }
        #pragma unroll
        for (int j = 0; j < 4; ++j) {             // B: hi + residual lo (scaled x256)
            float4 v = bR[j];
            v.x *= BSCALE; v.y *= BSCALE; v.z *= BSCALE; v.w *= BSCALE;
            uint2 h = pack_f16x4(v);
            float2 g0 = __half22float2(*reinterpret_cast<__half2*>(&h.x));
            float2 g1 = __half22float2(*reinterpret_cast<__half2*>(&h.y));
            float4 r = make_float4(v.x - g0.x, v.y - g0.y, v.z - g1.x, v.w - g1.y);
            uint2 l = pack_f16x4(r);
            char* rp = base + (lr + 32 * j) * ROWB + lc * 8;
            *reinterpret_cast<uint2*>(rp + OFF_BH) = h;
            *reinterpret_cast<uint2*>(rp + OFF_BL) = l;
        }
    };

    // ---- ldmatrix per-lane base offsets ----
    const int mi = lane >> 3, rowin = lane & 7;
    // A x4 matrices: (m+0,k+0),(m+8,k+0),(m+0,k+16B),(m+8,k+16B)
    const unsigned a_lane =
        (unsigned)((wm * 32 + (mi & 1) * 8 + rowin) * ROWB + (mi >> 1) * 16);
    // B x4 matrices: (n+0,k+0),(n+0,k+16B),(n+8,k+0),(n+8,k+16B)
    const unsigned b_lane =
        (unsigned)((wn * 32 + (mi >> 1) * 8 + rowin) * ROWB + (mi & 1) * 16);

    float acc[2][4][4];
    #pragma unroll
    for (int i = 0; i < 2; ++i)
        #pragma unroll
        for (int j = 0; j < 4; ++j)
            #pragma unroll
            for (int q = 0; q < 4; ++q) acc[i][j][q] = 0.0f;

    auto COMPUTE = [&](int buf) {
        const unsigned base = sb + (unsigned)(buf * STAGE);
        #pragma unroll
        for (int ks = 0; ks < 2; ++ks) {          // two k16 steps per BK=32
            unsigned aF[2][4], bH[2][4], bL[2][4];
            #pragma unroll
            for (int ma = 0; ma < 2; ++ma)
                ldsm4(aF[ma], base + a_lane + ma * (16 * ROWB) + ks * 32);
            #pragma unroll
            for (int g = 0; g < 2; ++g)
                ldsm4(bH[g], base + OFF_BH + b_lane + g * (16 * ROWB) + ks * 32);
            #pragma unroll
            for (int g = 0; g < 2; ++g)
                ldsm4(bL[g], base + OFF_BL + b_lane + g * (16 * ROWB) + ks * 32);
            #pragma unroll
            for (int ma = 0; ma < 2; ++ma)
                #pragma unroll
                for (int na = 0; na < 4; ++na) {
                    mma16816(acc[ma][na], aF[ma], &bH[na >> 1][(na & 1) * 2]);
                    mma16816(acc[ma][na], aF[ma], &bL[na >> 1][(na & 1) * 2]);
                }
        }
    };

    // ---- mainloop: double buffer, one sync per iteration ----
    LOAD(0);
    #pragma unroll 1
    for (int i = 0; i < NT; ++i) {
        const int buf = i & 1;
        STORE(buf);
        __syncthreads();
        if (i + 1 < NT) LOAD(i + 1);              // LDG latency hides under MMAs
        COMPUTE(buf);
    }

    // ---- epilogue: D frag rows l/4 (+8), cols (l%4)*2 (+1) ----
    const int orow0 = m0 + wm * 32 + (lane >> 2);
    const int ocol0 = n0 + wn * 32 + (lane & 3) * 2;
    #pragma unroll
    for (int ma = 0; ma < 2; ++ma) {
        #pragma unroll
        for (int na = 0; na < 4; ++na) {
            const int row = orow0 + ma * 16;
            const int col = ocol0 + na * 8;
            const float2 bb = *reinterpret_cast<const float2*>(bias + col);
            float2 v0 = make_float2(acc[ma][na][0] * OSCALE + bb.x,
                                    acc[ma][na][1] * OSCALE + bb.y);
            float2 v1 = make_float2(acc[ma][na][2] * OSCALE + bb.x,
                                    acc[ma][na][3] * OSCALE + bb.y);
            *reinterpret_cast<float2*>(O + (size_t)row * N + col)       = v0;
            *reinterpret_cast<float2*>(O + (size_t)(row + 8) * N + col) = v1;
        }
    }
}

extern "C" void kernel_launch(void* const* d_in, const int* in_sizes, int n_in,
                              void* d_out, int out_size)
{
    (void)in_sizes; (void)n_in; (void)out_size;
    const float* x    = (const float*)d_in[0];
    const float* w    = (const float*)d_in[1];
    const float* bias = (const float*)d_in[2];
    float* out        = (float*)d_out;

    static bool attr_set = false;
    if (!attr_set) {
        cudaFuncSetAttribute(memristor_hmma_kernel,
                             cudaFuncAttributeMaxDynamicSharedMemorySize, SMEM_TOTAL);
        attr_set = true;
    }
    dim3 grid(N / BN, M / BM);   // 16 x 8 = 128 CTAs
    memristor_hmma_kernel<<<grid, 256, SMEM_TOTAL>>>(x, w, bias, out);
}

// round 8
// speedup vs baseline: 4.5579x; 1.1530x over previous
#include <cuda_runtime.h>
#include <cuda_fp16.h>
#include <cstdint>

// out = x @ W^T + bias  (memristor constants cancel algebraically; see R1).
// Legacy HMMA (mma.sync.m16n8k16) path — harness compiles at compute_103, so
// tcgen05/TMEM are unavailable.
//
// 2-term fp16 split:  out ~= A_hi@(B_hi + B_lo),  B scaled by 256; 1/256 folded
// into the epilogue. rel_err ~2e-4 (measured R6).
//
// R7: in-CTA split-K. 512 threads = 2 k-groups x 8 warps; each group owns half
// of K with its own double-buffered stage pair + named barrier. Group 1 spills
// fp32 partials to SMEM; group 0 reduces + bias + stores. Doubles warps/SMSP
// (2 -> 4) to hide LDSM/HMMA latency; grid stays 128 CTAs ~ 1/SM.

namespace {
constexpr int M = 512, N = 2048, K = 2048;
constexpr int BM = 64, BN = 128, BK = 32;
constexpr int NT_G = (K / 2) / BK;         // 32 k-tiles per group
constexpr int ROWB = 80;                   // 64B data + 16B pad: conflict-free LDSM
constexpr int A_SZ   = BM * ROWB;          // 5120
constexpr int B_SZ   = BN * ROWB;          // 10240
constexpr int OFF_BH = A_SZ;
constexpr int OFF_BL = A_SZ + B_SZ;
constexpr int STAGE  = A_SZ + 2 * B_SZ;    // 25600
constexpr int SMEM_TOTAL = 4 * STAGE;      // 102400: [group0 buf0,buf1, group1 buf0,buf1]
constexpr float BSCALE = 256.0f;
constexpr float OSCALE = 1.0f / 256.0f;
}  // namespace

__device__ __forceinline__ unsigned smem_u32(const void* p) {
    unsigned a;
    asm("{ .reg .u64 t; cvta.to.shared.u64 t, %1; cvt.u32.u64 %0, t; }"
        : "=r"(a) : "l"(p));
    return a;
}

__device__ __forceinline__ void ldsm4(unsigned r[4], unsigned addr) {
    asm volatile("ldmatrix.sync.aligned.m8n8.x4.shared.b16 {%0,%1,%2,%3}, [%4];"
                 : "=r"(r[0]), "=r"(r[1]), "=r"(r[2]), "=r"(r[3]) : "r"(addr));
}

__device__ __forceinline__ void mma16816(float d[4], const unsigned a[4],
                                         const unsigned b[2]) {
    asm volatile(
        "mma.sync.aligned.m16n8k16.row.col.f32.f16.f16.f32 "
        "{%0,%1,%2,%3}, {%4,%5,%6,%7}, {%8,%9}, {%0,%1,%2,%3};"
        : "+f"(d[0]), "+f"(d[1]), "+f"(d[2]), "+f"(d[3])
        : "r"(a[0]), "r"(a[1]), "r"(a[2]), "r"(a[3]), "r"(b[0]), "r"(b[1]));
}

__device__ __forceinline__ uint2 pack_f16x4(float4 v) {
    unsigned h0, h1;
    asm("cvt.rn.f16x2.f32 %0, %1, %2;" : "=r"(h0) : "f"(v.y), "f"(v.x));
    asm("cvt.rn.f16x2.f32 %0, %1, %2;" : "=r"(h1) : "f"(v.w), "f"(v.z));
    return make_uint2(h0, h1);
}

__global__ __launch_bounds__(512, 1)
void memristor_hmma_kernel(const float* __restrict__ X, const float* __restrict__ W,
                           const float* __restrict__ bias, float* __restrict__ O)
{
    extern __shared__ char smem[];
    const unsigned sb = smem_u32(smem);
    const int t = threadIdx.x;
    const int lane = t & 31, wid = t >> 5;
    const int kg = wid >> 3;                      // k-group 0/1
    const int wl = wid & 7;                       // warp within group
    const int wm = wl & 1, wn = wl >> 1;          // warp grid 2(M) x 4(N)
    const int m0 = blockIdx.y * BM, n0 = blockIdx.x * BN;
    char* gbase0 = smem + kg * 2 * STAGE;

    // ---- global-load mapping within the group (256 threads) ----
    const int tl = t & 255;
    const int lr = tl >> 3;                       // 0..31
    const int lc = tl & 7;                        // float4 column
    const int kbase = kg * (K / 2);
    const float* aP = X + (size_t)(m0 + lr) * K + kbase + lc * 4;
    const float* bP = W + (size_t)(n0 + lr) * K + kbase + lc * 4;

    float4 aR[2], bR[4];
    auto LOAD = [&](int it) {
        const int k0 = it * BK;
        aR[0] = *reinterpret_cast<const float4*>(aP + k0);
        aR[1] = *reinterpret_cast<const float4*>(aP + (size_t)32 * K + k0);
        #pragma unroll
        for (int j = 0; j < 4; ++j)
            bR[j] = *reinterpret_cast<const float4*>(bP + (size_t)(32 * j) * K + k0);
    };

    auto STORE = [&](int buf) {
        char* base = gbase0 + buf * STAGE;
        #pragma unroll
        for (int j = 0; j < 2; ++j) {             // A: hi only
            uint2 h = pack_f16x4(aR[j]);
            *reinterpret_cast<uint2*>(base + (lr + 32 * j) * ROWB + lc * 8) = h;
        }
        #pragma unroll
        for (int j = 0; j < 4; ++j) {             // B: hi + residual lo (x256)
            float4 v = bR[j];
            v.x *= BSCALE; v.y *= BSCALE; v.z *= BSCALE; v.w *= BSCALE;
            uint2 h = pack_f16x4(v);
            float2 g0 = __half22float2(*reinterpret_cast<__half2*>(&h.x));
            float2 g1 = __half22float2(*reinterpret_cast<__half2*>(&h.y));
            float4 r = make_float4(v.x - g0.x, v.y - g0.y, v.z - g1.x, v.w - g1.y);
            uint2 l = pack_f16x4(r);
            char* rp = base + (lr + 32 * j) * ROWB + lc * 8;
            *reinterpret_cast<uint2*>(rp + OFF_BH) = h;
            *reinterpret_cast<uint2*>(rp + OFF_BL) = l;
        }
    };

    // ---- ldmatrix per-lane base offsets ----
    const int mi = lane >> 3, rowin = lane & 7;
    const unsigned a_lane =
        (unsigned)((wm * 32 + (mi & 1) * 8 + rowin) * ROWB + (mi >> 1) * 16);
    const unsigned b_lane =
        (unsigned)((wn * 32 + (mi >> 1) * 8 + rowin) * ROWB + (mi & 1) * 16);
    const unsigned gsb = sb + (unsigned)(kg * 2 * STAGE);

    float acc[2][4][4];
    #pragma unroll
    for (int i = 0; i < 2; ++i)
        #pragma unroll
        for (int j = 0; j < 4; ++j)
            #pragma unroll
            for (int q = 0; q < 4; ++q) acc[i][j][q] = 0.0f;

    auto COMPUTE = [&](int buf) {
        const unsigned base = gsb + (unsigned)(buf * STAGE);
        #pragma unroll
        for (int ks = 0; ks < 2; ++ks) {
            unsigned aF[2][4], bH[2][4], bL[2][4];
            #pragma unroll
            for (int ma = 0; ma < 2; ++ma)
                ldsm4(aF[ma], base + a_lane + ma * (16 * ROWB) + ks * 32);
            #pragma unroll
            for (int g = 0; g < 2; ++g)
                ldsm4(bH[g], base + OFF_BH + b_lane + g * (16 * ROWB) + ks * 32);
            #pragma unroll
            for (int g = 0; g < 2; ++g)
                ldsm4(bL[g], base + OFF_BL + b_lane + g * (16 * ROWB) + ks * 32);
            #pragma unroll
            for (int ma = 0; ma < 2; ++ma)
                #pragma unroll
                for (int na = 0; na < 4; ++na) {
                    mma16816(acc[ma][na], aF[ma], &bH[na >> 1][(na & 1) * 2]);
                    mma16816(acc[ma][na], aF[ma], &bL[na >> 1][(na & 1) * 2]);
                }
        }
    };

    // Named barrier per group so the two k-groups don't false-couple.
    auto GBAR = [&]() {
        asm volatile("bar.sync %0, %1;" :: "r"(kg + 1), "r"(256) : "memory");
    };

    // ---- mainloop ----
    LOAD(0);
    #pragma unroll 1
    for (int i = 0; i < NT_G; ++i) {
        const int buf = i & 1;
        STORE(buf);
        GBAR();
        if (i + 1 < NT_G) LOAD(i + 1);
        COMPUTE(buf);
        GBAR();                                   // buffer reusable next round
    }

    // ---- cross-group reduction: group1 -> SMEM fp32 tile, group0 reduces ----
    float* red = reinterpret_cast<float*>(smem);  // 64x128 f32 = 32KB, aliases stages
    const int frow0 = wm * 32 + (lane >> 2);
    const int fcol0 = wn * 32 + (lane & 3) * 2;

    __syncthreads();                              // all mainloop SMEM reads done
    if (kg == 1) {
        #pragma unroll
        for (int ma = 0; ma < 2; ++ma)
            #pragma unroll
            for (int na = 0; na < 4; ++na) {
                const int r = frow0 + ma * 16, c = fcol0 + na * 8;
                *reinterpret_cast<float2*>(&red[r * BN + c]) =
                    make_float2(acc[ma][na][0], acc[ma][na][1]);
                *reinterpret_cast<float2*>(&red[(r + 8) * BN + c]) =
                    make_float2(acc[ma][na][2], acc[ma][na][3]);
            }
    }
    __syncthreads();
    if (kg == 0) {
        #pragma unroll
        for (int ma = 0; ma < 2; ++ma)
            #pragma unroll
            for (int na = 0; na < 4; ++na) {
                const int r = frow0 + ma * 16, c = fcol0 + na * 8;
                const int row = m0 + r, col = n0 + c;
                const float2 bb = *reinterpret_cast<const float2*>(bias + col);
                const float2 p0 = *reinterpret_cast<const float2*>(&red[r * BN + c]);
                const float2 p1 = *reinterpret_cast<const float2*>(&red[(r + 8) * BN + c]);
                float2 v0 = make_float2((acc[ma][na][0] + p0.x) * OSCALE * BSCALE, 0.f);
                // NOTE: both groups' accs carry the same x256 B scale; single rescale.
                v0 = make_float2((acc[ma][na][0] + p0.x) * OSCALE + bb.x,
                                 (acc[ma][na][1] + p0.y) * OSCALE + bb.y);
                float2 v1 = make_float2((acc[ma][na][2] + p1.x) * OSCALE + bb.x,
                                        (acc[ma][na][3] + p1.y) * OSCALE + bb.y);
                *reinterpret_cast<float2*>(O + (size_t)row * N + col)       = v0;
                *reinterpret_cast<float2*>(O + (size_t)(row + 8) * N + col) = v1;
            }
    }
}

extern "C" void kernel_launch(void* const* d_in, const int* in_sizes, int n_in,
                              void* d_out, int out_size)
{
    (void)in_sizes; (void)n_in; (void)out_size;
    const float* x    = (const float*)d_in[0];
    const float* w    = (const float*)d_in[1];
    const float* bias = (const float*)d_in[2];
    float* out        = (float*)d_out;

    static bool attr_set = false;
    if (!attr_set) {
        cudaFuncSetAttribute(memristor_hmma_kernel,
                             cudaFuncAttributeMaxDynamicSharedMemorySize, SMEM_TOTAL);
        attr_set = true;
    }
    dim3 grid(N / BN, M / BM);   // 16 x 8 = 128 CTAs
    memristor_hmma_kernel<<<grid, 512, SMEM_TOTAL>>>(x, w, bias, out);
}

// round 9
// speedup vs baseline: 6.5683x; 1.4411x over previous
#include <cuda_runtime.h>
#include <cuda_fp16.h>
#include <cstdint>

// out = x @ W^T + bias  (memristor constants cancel algebraically; see R1).
// Legacy HMMA (mma.sync.m16n8k16) path — harness compiles at compute_103, so
// tcgen05/TMEM are unavailable.
//
// R9: pure fp16 single-term GEMM. Measured R6/R8 rel_err (2.078e-4) isolates
// the A-side fp16 rounding; adding B-side rounding gives ~sqrt(2)*2.08e-4
// ~= 2.9e-4, still 3.4x under the 1e-3 gate. Halves MMA work and SMEM traffic
// vs the 2-term split. BK=32 -> 64 halves barrier count. Split-K x2 retained:
// 512 threads = 2 k-groups x 8 warps, per-group double buffer + named barrier.

namespace {
constexpr int M = 512, N = 2048, K = 2048;
constexpr int BM = 64, BN = 128, BK = 64;
constexpr int NT_G = (K / 2) / BK;         // 16 k-tiles per group
constexpr int ROWB = 144;                  // 128B data + 16B pad (144%128=16 -> LDSM conflict-free)
constexpr int A_SZ  = BM * ROWB;           // 9216
constexpr int B_SZ  = BN * ROWB;           // 18432
constexpr int OFF_B = A_SZ;
constexpr int STAGE = A_SZ + B_SZ;         // 27648
constexpr int SMEM_TOTAL = 4 * STAGE;      // 110592: [g0 buf0,buf1, g1 buf0,buf1]
}  // namespace

__device__ __forceinline__ unsigned smem_u32(const void* p) {
    unsigned a;
    asm("{ .reg .u64 t; cvta.to.shared.u64 t, %1; cvt.u32.u64 %0, t; }"
        : "=r"(a) : "l"(p));
    return a;
}

__device__ __forceinline__ void ldsm4(unsigned r[4], unsigned addr) {
    asm volatile("ldmatrix.sync.aligned.m8n8.x4.shared.b16 {%0,%1,%2,%3}, [%4];"
                 : "=r"(r[0]), "=r"(r[1]), "=r"(r[2]), "=r"(r[3]) : "r"(addr));
}

__device__ __forceinline__ void mma16816(float d[4], const unsigned a[4],
                                         const unsigned b[2]) {
    asm volatile(
        "mma.sync.aligned.m16n8k16.row.col.f32.f16.f16.f32 "
        "{%0,%1,%2,%3}, {%4,%5,%6,%7}, {%8,%9}, {%0,%1,%2,%3};"
        : "+f"(d[0]), "+f"(d[1]), "+f"(d[2]), "+f"(d[3])
        : "r"(a[0]), "r"(a[1]), "r"(a[2]), "r"(a[3]), "r"(b[0]), "r"(b[1]));
}

__device__ __forceinline__ uint2 pack_f16x4(float4 v) {
    unsigned h0, h1;
    asm("cvt.rn.f16x2.f32 %0, %1, %2;" : "=r"(h0) : "f"(v.y), "f"(v.x));
    asm("cvt.rn.f16x2.f32 %0, %1, %2;" : "=r"(h1) : "f"(v.w), "f"(v.z));
    return make_uint2(h0, h1);
}

__global__ __launch_bounds__(512, 1)
void memristor_hmma_kernel(const float* __restrict__ X, const float* __restrict__ W,
                           const float* __restrict__ bias, float* __restrict__ O)
{
    extern __shared__ char smem[];
    const unsigned sb = smem_u32(smem);
    const int t = threadIdx.x;
    const int lane = t & 31, wid = t >> 5;
    const int kg = wid >> 3;                      // k-group 0/1
    const int wl = wid & 7;                       // warp within group
    const int wm = wl & 1, wn = wl >> 1;          // warp grid 2(M) x 4(N)
    const int m0 = blockIdx.y * BM, n0 = blockIdx.x * BN;
    char* gbase0 = smem + kg * 2 * STAGE;

    // ---- global-load mapping within the group (256 threads) ----
    // Tile rows of 64 f32 = 16 float4; thread covers (row lr+16j, col lc).
    const int tl = t & 255;
    const int lr = tl >> 4;                       // 0..15
    const int lc = tl & 15;                       // float4 column 0..15
    const int kbase = kg * (K / 2);
    const float* aP = X + (size_t)(m0 + lr) * K + kbase + lc * 4;
    const float* bP = W + (size_t)(n0 + lr) * K + kbase + lc * 4;

    float4 aR[4], bR[8];
    auto LOAD = [&](int it) {
        const int k0 = it * BK;
        #pragma unroll
        for (int j = 0; j < 4; ++j)
            aR[j] = *reinterpret_cast<const float4*>(aP + (size_t)(16 * j) * K + k0);
        #pragma unroll
        for (int j = 0; j < 8; ++j)
            bR[j] = *reinterpret_cast<const float4*>(bP + (size_t)(16 * j) * K + k0);
    };

    auto STORE = [&](int buf) {
        char* base = gbase0 + buf * STAGE;
        #pragma unroll
        for (int j = 0; j < 4; ++j)
            *reinterpret_cast<uint2*>(base + (lr + 16 * j) * ROWB + lc * 8) =
                pack_f16x4(aR[j]);
        #pragma unroll
        for (int j = 0; j < 8; ++j)
            *reinterpret_cast<uint2*>(base + OFF_B + (lr + 16 * j) * ROWB + lc * 8) =
                pack_f16x4(bR[j]);
    };

    // ---- ldmatrix per-lane base offsets ----
    const int mi = lane >> 3, rowin = lane & 7;
    // A x4: (m+0,k0),(m+8,k0),(m+0,k0+16B),(m+8,k0+16B)
    const unsigned a_lane =
        (unsigned)((wm * 32 + (mi & 1) * 8 + rowin) * ROWB + (mi >> 1) * 16);
    // B x4: (n+0,k0),(n+0,k0+16B),(n+8,k0),(n+8,k0+16B)
    const unsigned b_lane =
        (unsigned)((wn * 32 + (mi >> 1) * 8 + rowin) * ROWB + (mi & 1) * 16);
    const unsigned gsb = sb + (unsigned)(kg * 2 * STAGE);

    float acc[2][4][4];
    #pragma unroll
    for (int i = 0; i < 2; ++i)
        #pragma unroll
        for (int j = 0; j < 4; ++j)
            #pragma unroll
            for (int q = 0; q < 4; ++q) acc[i][j][q] = 0.0f;

    auto COMPUTE = [&](int buf) {
        const unsigned base = gsb + (unsigned)(buf * STAGE);
        #pragma unroll
        for (int ks = 0; ks < 4; ++ks) {          // four k16 steps per BK=64
            unsigned aF[2][4], bF[2][4];
            #pragma unroll
            for (int ma = 0; ma < 2; ++ma)
                ldsm4(aF[ma], base + a_lane + ma * (16 * ROWB) + ks * 32);
            #pragma unroll
            for (int g = 0; g < 2; ++g)
                ldsm4(bF[g], base + OFF_B + b_lane + g * (16 * ROWB) + ks * 32);
            #pragma unroll
            for (int ma = 0; ma < 2; ++ma)
                #pragma unroll
                for (int na = 0; na < 4; ++na)
                    mma16816(acc[ma][na], aF[ma], &bF[na >> 1][(na & 1) * 2]);
        }
    };

    auto GBAR = [&]() {
        asm volatile("bar.sync %0, %1;" :: "r"(kg + 1), "r"(256) : "memory");
    };

    // ---- mainloop ----
    LOAD(0);
    #pragma unroll 1
    for (int i = 0; i < NT_G; ++i) {
        const int buf = i & 1;
        STORE(buf);
        GBAR();
        if (i + 1 < NT_G) LOAD(i + 1);            // LDG latency hides under MMAs
        COMPUTE(buf);
        GBAR();                                   // buffer reusable next round
    }

    // ---- cross-group reduction: group1 -> SMEM fp32 tile, group0 reduces ----
    float* red = reinterpret_cast<float*>(smem);  // 64x128 f32 = 32KB, aliases stages
    const int frow0 = wm * 32 + (lane >> 2);
    const int fcol0 = wn * 32 + (lane & 3) * 2;

    __syncthreads();
    if (kg == 1) {
        #pragma unroll
        for (int ma = 0; ma < 2; ++ma)
            #pragma unroll
            for (int na = 0; na < 4; ++na) {
                const int r = frow0 + ma * 16, c = fcol0 + na * 8;
                *reinterpret_cast<float2*>(&red[r * BN + c]) =
                    make_float2(acc[ma][na][0], acc[ma][na][1]);
                *reinterpret_cast<float2*>(&red[(r + 8) * BN + c]) =
                    make_float2(acc[ma][na][2], acc[ma][na][3]);
            }
    }
    __syncthreads();
    if (kg == 0) {
        #pragma unroll
        for (int ma = 0; ma < 2; ++ma)
            #pragma unroll
            for (int na = 0; na < 4; ++na) {
                const int r = frow0 + ma * 16, c = fcol0 + na * 8;
                const int row = m0 + r, col = n0 + c;
                const float2 bb = *reinterpret_cast<const float2*>(bias + col);
                const float2 p0 = *reinterpret_cast<const float2*>(&red[r * BN + c]);
                const float2 p1 = *reinterpret_cast<const float2*>(&red[(r + 8) * BN + c]);
                float2 v0 = make_float2(acc[ma][na][0] + p0.x + bb.x,
                                        acc[ma][na][1] + p0.y + bb.y);
                float2 v1 = make_float2(acc[ma][na][2] + p1.x + bb.x,
                                        acc[ma][na][3] + p1.y + bb.y);
                *reinterpret_cast<float2*>(O + (size_t)row * N + col)       = v0;
                *reinterpret_cast<float2*>(O + (size_t)(row + 8) * N + col) = v1;
            }
    }
}

extern "C" void kernel_launch(void* const* d_in, const int* in_sizes, int n_in,
                              void* d_out, int out_size)
{
    (void)in_sizes; (void)n_in; (void)out_size;
    const float* x    = (const float*)d_in[0];
    const float* w    = (const float*)d_in[1];
    const float* bias = (const float*)d_in[2];
    float* out        = (float*)d_out;

    static bool attr_set = false;
    if (!attr_set) {
        cudaFuncSetAttribute(memristor_hmma_kernel,
                             cudaFuncAttributeMaxDynamicSharedMemorySize, SMEM_TOTAL);
        attr_set = true;
    }
    dim3 grid(N / BN, M / BM);   // 16 x 8 = 128 CTAs
    memristor_hmma_kernel<<<grid, 512, SMEM_TOTAL>>>(x, w, bias, out);
}

// round 12
// speedup vs baseline: 6.5759x; 1.0012x over previous
#include <cuda_runtime.h>
#include <cuda_fp16.h>
#include <cstdint>

// out = x @ W^T + bias  (memristor constants cancel algebraically; see R1).
// Legacy HMMA (mma.sync.m16n8k16) — harness targets compute_103, no tcgen05.
//
// fp16 single-term GEMM (rel_err 2.93e-4 measured, gate is 1e-3).
// Split-K x2: 512 threads = 2 k-groups x 8 warps, per-group stage ring.
//
// R10/R11: 3-stage ring, ONE named barrier per iteration (was 2 with double
// buffer). Safety: warp at STORE(i) passed bar(i-1) => all warps did
// STORE(i-1) => (program order) all did COMPUTE(i-2) >= last reader of
// buffer i%3. bar(i) orders STORE(i) before COMPUTE(i) reads. Halves
// barrier serialization and lets fast warps run a full iter ahead.
// (R10 bench hit an infra failure; identical resubmission.)

namespace {
constexpr int M = 512, N = 2048, K = 2048;
constexpr int BM = 64, BN = 128, BK = 64;
constexpr int NT_G = (K / 2) / BK;         // 16 k-tiles per group
constexpr int ROWB = 144;                  // 128B data + 16B pad: LDSM conflict-free
constexpr int A_SZ  = BM * ROWB;           // 9216
constexpr int B_SZ  = BN * ROWB;           // 18432
constexpr int OFF_B = A_SZ;
constexpr int STAGE = A_SZ + B_SZ;         // 27648
constexpr int NSTG  = 3;
constexpr int SMEM_TOTAL = 2 * NSTG * STAGE;  // 165888
}  // namespace

__device__ __forceinline__ unsigned smem_u32(const void* p) {
    unsigned a;
    asm("{ .reg .u64 t; cvta.to.shared.u64 t, %1; cvt.u32.u64 %0, t; }"
        : "=r"(a) : "l"(p));
    return a;
}

__device__ __forceinline__ void ldsm4(unsigned r[4], unsigned addr) {
    asm volatile("ldmatrix.sync.aligned.m8n8.x4.shared.b16 {%0,%1,%2,%3}, [%4];"
                 : "=r"(r[0]), "=r"(r[1]), "=r"(r[2]), "=r"(r[3]) : "r"(addr));
}

__device__ __forceinline__ void mma16816(float d[4], const unsigned a[4],
                                         const unsigned b[2]) {
    asm volatile(
        "mma.sync.aligned.m16n8k16.row.col.f32.f16.f16.f32 "
        "{%0,%1,%2,%3}, {%4,%5,%6,%7}, {%8,%9}, {%0,%1,%2,%3};"
        : "+f"(d[0]), "+f"(d[1]), "+f"(d[2]), "+f"(d[3])
        : "r"(a[0]), "r"(a[1]), "r"(a[2]), "r"(a[3]), "r"(b[0]), "r"(b[1]));
}

__device__ __forceinline__ uint2 pack_f16x4(float4 v) {
    unsigned h0, h1;
    asm("cvt.rn.f16x2.f32 %0, %1, %2;" : "=r"(h0) : "f"(v.y), "f"(v.x));
    asm("cvt.rn.f16x2.f32 %0, %1, %2;" : "=r"(h1) : "f"(v.w), "f"(v.z));
    return make_uint2(h0, h1);
}

__global__ __launch_bounds__(512, 1)
void memristor_hmma_kernel(const float* __restrict__ X, const float* __restrict__ W,
                           const float* __restrict__ bias, float* __restrict__ O)
{
    extern __shared__ char smem[];
    const unsigned sb = smem_u32(smem);
    const int t = threadIdx.x;
    const int lane = t & 31, wid = t >> 5;
    const int kg = wid >> 3;                      // k-group 0/1
    const int wl = wid & 7;                       // warp within group
    const int wm = wl & 1, wn = wl >> 1;          // warp grid 2(M) x 4(N)
    const int m0 = blockIdx.y * BM, n0 = blockIdx.x * BN;
    char* gbase0 = smem + kg * NSTG * STAGE;

    // ---- global-load mapping within the group (256 threads) ----
    const int tl = t & 255;
    const int lr = tl >> 4;                       // 0..15
    const int lc = tl & 15;                       // float4 column
    const int kbase = kg * (K / 2);
    const float* aP = X + (size_t)(m0 + lr) * K + kbase + lc * 4;
    const float* bP = W + (size_t)(n0 + lr) * K + kbase + lc * 4;

    float4 aR[4], bR[8];
    auto LOAD = [&](int it) {
        const int k0 = it * BK;
        #pragma unroll
        for (int j = 0; j < 4; ++j)
            aR[j] = *reinterpret_cast<const float4*>(aP + (size_t)(16 * j) * K + k0);
        #pragma unroll
        for (int j = 0; j < 8; ++j)
            bR[j] = *reinterpret_cast<const float4*>(bP + (size_t)(16 * j) * K + k0);
    };

    auto STORE = [&](int buf) {
        char* base = gbase0 + buf * STAGE;
        #pragma unroll
        for (int j = 0; j < 4; ++j)
            *reinterpret_cast<uint2*>(base + (lr + 16 * j) * ROWB + lc * 8) =
                pack_f16x4(aR[j]);
        #pragma unroll
        for (int j = 0; j < 8; ++j)
            *reinterpret_cast<uint2*>(base + OFF_B + (lr + 16 * j) * ROWB + lc * 8) =
                pack_f16x4(bR[j]);
    };

    // ---- ldmatrix per-lane base offsets ----
    const int mi = lane >> 3, rowin = lane & 7;
    const unsigned a_lane =
        (unsigned)((wm * 32 + (mi & 1) * 8 + rowin) * ROWB + (mi >> 1) * 16);
    const unsigned b_lane =
        (unsigned)((wn * 32 + (mi >> 1) * 8 + rowin) * ROWB + (mi & 1) * 16);
    const unsigned gsb = sb + (unsigned)(kg * NSTG * STAGE);

    float acc[2][4][4];
    #pragma unroll
    for (int i = 0; i < 2; ++i)
        #pragma unroll
        for (int j = 0; j < 4; ++j)
            #pragma unroll
            for (int q = 0; q < 4; ++q) acc[i][j][q] = 0.0f;

    auto COMPUTE = [&](int buf) {
        const unsigned base = gsb + (unsigned)(buf * STAGE);
        #pragma unroll
        for (int ks = 0; ks < 4; ++ks) {          // four k16 steps per BK=64
            unsigned aF[2][4], bF[2][4];
            #pragma unroll
            for (int ma = 0; ma < 2; ++ma)
                ldsm4(aF[ma], base + a_lane + ma * (16 * ROWB) + ks * 32);
            #pragma unroll
            for (int g = 0; g < 2; ++g)
                ldsm4(bF[g], base + OFF_B + b_lane + g * (16 * ROWB) + ks * 32);
            #pragma unroll
            for (int ma = 0; ma < 2; ++ma)
                #pragma unroll
                for (int na = 0; na < 4; ++na)
                    mma16816(acc[ma][na], aF[ma], &bF[na >> 1][(na & 1) * 2]);
        }
    };

    auto GBAR = [&]() {
        asm volatile("bar.sync %0, %1;" :: "r"(kg + 1), "r"(256) : "memory");
    };

    // ---- mainloop: 3-stage ring, one barrier per iteration ----
    LOAD(0);
    int buf = 0;
    #pragma unroll 1
    for (int i = 0; i < NT_G; ++i) {
        STORE(buf);
        GBAR();
        if (i + 1 < NT_G) LOAD(i + 1);            // LDG hides under COMPUTE
        COMPUTE(buf);
        buf = (buf == NSTG - 1) ? 0 : buf + 1;
    }

    // ---- cross-group reduction: group1 -> SMEM fp32 tile, group0 reduces ----
    float* red = reinterpret_cast<float*>(smem);  // 64x128 f32 = 32KB, aliases stages
    const int frow0 = wm * 32 + (lane >> 2);
    const int fcol0 = wn * 32 + (lane & 3) * 2;

    __syncthreads();
    if (kg == 1) {
        #pragma unroll
        for (int ma = 0; ma < 2; ++ma)
            #pragma unroll
            for (int na = 0; na < 4; ++na) {
                const int r = frow0 + ma * 16, c = fcol0 + na * 8;
                *reinterpret_cast<float2*>(&red[r * BN + c]) =
                    make_float2(acc[ma][na][0], acc[ma][na][1]);
                *reinterpret_cast<float2*>(&red[(r + 8) * BN + c]) =
                    make_float2(acc[ma][na][2], acc[ma][na][3]);
            }
    }
    __syncthreads();
    if (kg == 0) {
        #pragma unroll
        for (int ma = 0; ma < 2; ++ma)
            #pragma unroll
            for (int na = 0; na < 4; ++na) {
                const int r = frow0 + ma * 16, c = fcol0 + na * 8;
                const int row = m0 + r, col = n0 + c;
                const float2 bb = *reinterpret_cast<const float2*>(bias + col);
                const float2 p0 = *reinterpret_cast<const float2*>(&red[r * BN + c]);
                const float2 p1 = *reinterpret_cast<const float2*>(&red[(r + 8) * BN + c]);
                float2 v0 = make_float2(acc[ma][na][0] + p0.x + bb.x,
                                        acc[ma][na][1] + p0.y + bb.y);
                float2 v1 = make_float2(acc[ma][na][2] + p1.x + bb.x,
                                        acc[ma][na][3] + p1.y + bb.y);
                *reinterpret_cast<float2*>(O + (size_t)row * N + col)       = v0;
                *reinterpret_cast<float2*>(O + (size_t)(row + 8) * N + col) = v1;
            }
    }
}

extern "C" void kernel_launch(void* const* d_in, const int* in_sizes, int n_in,
                              void* d_out, int out_size)
{
    (void)in_sizes; (void)n_in; (void)out_size;
    const float* x    = (const float*)d_in[0];
    const float* w    = (const float*)d_in[1];
    const float* bias = (const float*)d_in[2];
    float* out        = (float*)d_out;

    static bool attr_set = false;
    if (!attr_set) {
        cudaFuncSetAttribute(memristor_hmma_kernel,
                             cudaFuncAttributeMaxDynamicSharedMemorySize, SMEM_TOTAL);
        attr_set = true;
    }
    dim3 grid(N / BN, M / BM);   // 16 x 8 = 128 CTAs
    memristor_hmma_kernel<<<grid, 512, SMEM_TOTAL>>>(x, w, bias, out);
}